// round 13
// baseline (speedup 1.0000x reference)
#include <cuda_runtime.h>
#include <cstdint>
#include <cstddef>

// ---------------- static scratch (no allocations allowed) ----------------
#define MAXN 50000
#define MAXE 800000

__device__ float g_dis[MAXN];          // degree, then D^-1/2 in place
__device__ int   g_cnt[MAXN];          // per-row edge counts
__device__ int   g_rowptr[MAXN + 1];
__device__ int   g_cursor[MAXN];
__device__ int   g_part[256];          // scan partials
__device__ int   g_cols[MAXE];         // CSR-sorted column ids
__device__ float g_enorm[MAXE];        // CSR-sorted per-edge norm
__device__ float g_bufA[MAXN * 100];   // 20 MB
__device__ float g_bufB[MAXN * 100];   // 20 MB

// ---------------- preprocessing kernels ----------------
__global__ void k_init(float* deg, int* cnt, int n) {
    int i = blockIdx.x * blockDim.x + threadIdx.x;
    if (i < n) { deg[i] = 1.0f; cnt[i] = 0; }   // self loop weight 1
}

__global__ void k_edge_deg(const int* __restrict__ row, const float* __restrict__ w,
                           float* deg, int* cnt, int e) {
    int i = blockIdx.x * blockDim.x + threadIdx.x;
    if (i < e) {
        int r = row[i];
        atomicAdd(&deg[r], w[i]);
        atomicAdd(&cnt[r], 1);
    }
}

__global__ void k_dis(float* deg, int n) {
    int i = blockIdx.x * blockDim.x + threadIdx.x;
    if (i < n) deg[i] = rsqrtf(deg[i]);   // deg >= 1 always
}

// ---- multi-block exclusive scan: reduce -> scan partials -> apply ----
__global__ void k_reduce(const int* __restrict__ cnt, int* __restrict__ part, int n) {
    __shared__ int ws[8];
    int i = blockIdx.x * 256 + threadIdx.x;
    int v = (i < n) ? cnt[i] : 0;
    #pragma unroll
    for (int off = 16; off > 0; off >>= 1) v += __shfl_down_sync(0xffffffffu, v, off);
    int lane = threadIdx.x & 31, w = threadIdx.x >> 5;
    if (lane == 0) ws[w] = v;
    __syncthreads();
    if (threadIdx.x == 0) {
        int s = 0;
        #pragma unroll
        for (int j = 0; j < 8; j++) s += ws[j];
        part[blockIdx.x] = s;
    }
}

// single block of 256 threads: exclusive scan of nb (<=256) partials, in place
__global__ void k_scanp(int* part, int nb) {
    __shared__ int ws[8];
    int tid = threadIdx.x;
    int lane = tid & 31, w = tid >> 5;
    int v = (tid < nb) ? part[tid] : 0;
    int x = v;
    #pragma unroll
    for (int off = 1; off < 32; off <<= 1) {
        int t = __shfl_up_sync(0xffffffffu, x, off);
        if (lane >= off) x += t;
    }
    if (lane == 31) ws[w] = x;
    __syncthreads();
    if (w == 0 && lane < 8) {
        int s = ws[lane];
        #pragma unroll
        for (int off = 1; off < 8; off <<= 1) {
            int t = __shfl_up_sync(0x000000ffu, s, off);
            if (lane >= off) s += t;
        }
        ws[lane] = s;
    }
    __syncthreads();
    int warp_excl = (w == 0) ? 0 : ws[w - 1];
    if (tid < nb) part[tid] = x + warp_excl - v;   // exclusive
}

__global__ void k_apply(const int* __restrict__ cnt, const int* __restrict__ part,
                        int* __restrict__ rowptr, int* __restrict__ cursor,
                        int n, int e) {
    __shared__ int ws[8];
    int tid = threadIdx.x;
    int lane = tid & 31, w = tid >> 5;
    int i = blockIdx.x * 256 + tid;
    int v = (i < n) ? cnt[i] : 0;
    int x = v;
    #pragma unroll
    for (int off = 1; off < 32; off <<= 1) {
        int t = __shfl_up_sync(0xffffffffu, x, off);
        if (lane >= off) x += t;
    }
    if (lane == 31) ws[w] = x;
    __syncthreads();
    if (w == 0 && lane < 8) {
        int s = ws[lane];
        #pragma unroll
        for (int off = 1; off < 8; off <<= 1) {
            int t = __shfl_up_sync(0x000000ffu, s, off);
            if (lane >= off) s += t;
        }
        ws[lane] = s;
    }
    __syncthreads();
    int warp_excl = (w == 0) ? 0 : ws[w - 1];
    int excl = x - v + warp_excl + part[blockIdx.x];
    if (i < n) { rowptr[i] = excl; cursor[i] = excl; }
    if (blockIdx.x == 0 && tid == 0) rowptr[n] = e;
}

__global__ void k_scatter(const int* __restrict__ row, const int* __restrict__ col,
                          const float* __restrict__ w, const float* __restrict__ dis,
                          int* cursor, int* __restrict__ ocol, float* __restrict__ onorm,
                          int e) {
    int i = blockIdx.x * blockDim.x + threadIdx.x;
    if (i < e) {
        int r = row[i];
        int c = col[i];
        int p = atomicAdd(&cursor[r], 1);
        ocol[p] = c;
        onorm[p] = dis[r] * w[i] * dis[c];
    }
}

// ---------------- GEMM: C[N x ldc] = A[N x K](lda) * B[K x F], pad cols zeroed ----------------
// 128x64 tile, BK=8, 256 threads, per-thread 8x4 register tile.
// Requires lda % 4 == 0 (holds: 128, 100, 100, 52).
#define BM 128
#define BN 64
#define BK 8

__global__ __launch_bounds__(256) void k_gemm(
    const float* __restrict__ A, int lda,
    const float* __restrict__ B,           // [K x F] row-major, stride F
    float* __restrict__ C, int ldc,
    int N, int K, int F) {
    __shared__ float As[BK][BM];
    __shared__ float Bs[BK][BN];

    int tid = threadIdx.x;
    int m0 = blockIdx.x * BM;
    int n0 = blockIdx.y * BN;
    int tx = tid & 15;   // 0..15 -> n
    int ty = tid >> 4;   // 0..15 -> m

    float acc[8][4];
    #pragma unroll
    for (int i = 0; i < 8; i++)
        #pragma unroll
        for (int j = 0; j < 4; j++) acc[i][j] = 0.f;

    for (int k0 = 0; k0 < K; k0 += BK) {
        // A tile: 128 rows x 8 k = 256 float4 loads, one per thread
        {
            int m  = tid >> 1;
            int kq = (tid & 1) * 4;
            int gm = m0 + m, gk = k0 + kq;
            float4 v = make_float4(0.f, 0.f, 0.f, 0.f);
            if (gm < N) {
                if (gk + 3 < K) {
                    v = *reinterpret_cast<const float4*>(A + (size_t)gm * lda + gk);
                } else {
                    const float* ar = A + (size_t)gm * lda;
                    if (gk + 0 < K) v.x = ar[gk + 0];
                    if (gk + 1 < K) v.y = ar[gk + 1];
                    if (gk + 2 < K) v.z = ar[gk + 2];
                    if (gk + 3 < K) v.w = ar[gk + 3];
                }
            }
            As[kq + 0][m] = v.x;
            As[kq + 1][m] = v.y;
            As[kq + 2][m] = v.z;
            As[kq + 3][m] = v.w;
        }
        // B tile: 8 x 64 = 512 elems, 2 per thread, coalesced
        #pragma unroll
        for (int i = 0; i < 2; i++) {
            int idx = tid + 256 * i;
            int k = idx >> 6;
            int nn = idx & 63;
            int gk = k0 + k, gn = n0 + nn;
            Bs[k][nn] = (gk < K && gn < F) ? B[(size_t)gk * F + gn] : 0.f;
        }
        __syncthreads();
        #pragma unroll
        for (int k = 0; k < BK; k++) {
            float4 a0 = *reinterpret_cast<const float4*>(&As[k][ty * 8]);
            float4 a1 = *reinterpret_cast<const float4*>(&As[k][ty * 8 + 4]);
            float4 b4 = *reinterpret_cast<const float4*>(&Bs[k][tx * 4]);
            float a[8] = {a0.x, a0.y, a0.z, a0.w, a1.x, a1.y, a1.z, a1.w};
            float b[4] = {b4.x, b4.y, b4.z, b4.w};
            #pragma unroll
            for (int i = 0; i < 8; i++)
                #pragma unroll
                for (int j = 0; j < 4; j++) acc[i][j] += a[i] * b[j];
        }
        __syncthreads();
    }

    #pragma unroll
    for (int i = 0; i < 8; i++) {
        int gm = m0 + ty * 8 + i;
        if (gm >= N) continue;
        #pragma unroll
        for (int j = 0; j < 4; j++) {
            int gn = n0 + tx * 4 + j;
            if (gn < F)        C[(size_t)gm * ldc + gn] = acc[i][j];
            else if (gn < ldc) C[(size_t)gm * ldc + gn] = 0.f;
        }
    }
}

// ---------------- aggregation: out[r] = bias + sum_e norm*h[col] + dis[r]^2*h[r] ----------------
// one warp per row; lane owns features [4*lane, 4*lane+4) of the padded stride SP
__global__ __launch_bounds__(256) void k_agg(
    const float* __restrict__ h, int SP,
    const int* __restrict__ rowptr,
    const int* __restrict__ cols,
    const float* __restrict__ enorm,
    const float* __restrict__ dis,
    const float* __restrict__ bias,
    float* __restrict__ out, int OS,
    int n, int F, int do_relu) {
    int wid = (blockIdx.x * blockDim.x + threadIdx.x) >> 5;
    int lane = threadIdx.x & 31;
    if (wid >= n) return;
    int row = wid;
    int f0 = lane * 4;
    bool active = f0 < SP;

    float4 acc0 = make_float4(0.f, 0.f, 0.f, 0.f);
    float4 acc1 = make_float4(0.f, 0.f, 0.f, 0.f);
    if (active) {
        float d = dis[row];
        float sn = d * d;
        float4 hv = *reinterpret_cast<const float4*>(h + (size_t)row * SP + f0);
        acc0.x = sn * hv.x + ((f0 + 0 < F) ? bias[f0 + 0] : 0.f);
        acc0.y = sn * hv.y + ((f0 + 1 < F) ? bias[f0 + 1] : 0.f);
        acc0.z = sn * hv.z + ((f0 + 2 < F) ? bias[f0 + 2] : 0.f);
        acc0.w = sn * hv.w + ((f0 + 3 < F) ? bias[f0 + 3] : 0.f);
    }

    int start = rowptr[row];
    int end = rowptr[row + 1];
    for (int eb = start; eb < end; eb += 32) {
        int idx = eb + lane;
        int c_l = 0;
        float v_l = 0.f;
        if (idx < end) { c_l = cols[idx]; v_l = enorm[idx]; }
        int cnt = min(32, end - eb);
        int i = 0;
        for (; i + 1 < cnt; i += 2) {
            int c0 = __shfl_sync(0xffffffffu, c_l, i);
            float v0 = __shfl_sync(0xffffffffu, v_l, i);
            int c1 = __shfl_sync(0xffffffffu, c_l, i + 1);
            float v1 = __shfl_sync(0xffffffffu, v_l, i + 1);
            if (active) {
                float4 h0 = *reinterpret_cast<const float4*>(h + (size_t)c0 * SP + f0);
                float4 h1 = *reinterpret_cast<const float4*>(h + (size_t)c1 * SP + f0);
                acc0.x += v0 * h0.x; acc0.y += v0 * h0.y;
                acc0.z += v0 * h0.z; acc0.w += v0 * h0.w;
                acc1.x += v1 * h1.x; acc1.y += v1 * h1.y;
                acc1.z += v1 * h1.z; acc1.w += v1 * h1.w;
            }
        }
        if (i < cnt) {
            int c0 = __shfl_sync(0xffffffffu, c_l, i);
            float v0 = __shfl_sync(0xffffffffu, v_l, i);
            if (active) {
                float4 h0 = *reinterpret_cast<const float4*>(h + (size_t)c0 * SP + f0);
                acc0.x += v0 * h0.x; acc0.y += v0 * h0.y;
                acc0.z += v0 * h0.z; acc0.w += v0 * h0.w;
            }
        }
    }
    if (!active) return;
    float4 acc = make_float4(acc0.x + acc1.x, acc0.y + acc1.y,
                             acc0.z + acc1.z, acc0.w + acc1.w);
    if (do_relu) {
        acc.x = fmaxf(acc.x, 0.f);
        acc.y = fmaxf(acc.y, 0.f);
        acc.z = fmaxf(acc.z, 0.f);
        acc.w = fmaxf(acc.w, 0.f);
    }
    if (OS == SP) {
        *reinterpret_cast<float4*>(out + (size_t)row * OS + f0) = acc;
    } else {
        float a[4] = {acc.x, acc.y, acc.z, acc.w};
        #pragma unroll
        for (int j = 0; j < 4; j++) {
            int f = f0 + j;
            if (f < OS) out[(size_t)row * OS + f] = a[j];
        }
    }
}

// ---------------- launch ----------------
static inline int cdiv(int a, int b) { return (a + b - 1) / b; }

extern "C" void kernel_launch(void* const* d_in, const int* in_sizes, int n_in,
                              void* d_out, int out_size) {
    const float* x  = (const float*)d_in[0];
    const int*   ei = (const int*)d_in[1];
    const float* ew = (const float*)d_in[2];
    const float* W0 = (const float*)d_in[3];
    const float* b0 = (const float*)d_in[4];
    const float* W1 = (const float*)d_in[5];
    const float* b1 = (const float*)d_in[6];
    const float* W2 = (const float*)d_in[7];
    const float* b2 = (const float*)d_in[8];
    const float* W3 = (const float*)d_in[9];
    const float* b3 = (const float*)d_in[10];

    int N = in_sizes[0] / 128;
    int E = in_sizes[1] / 2;
    const int* row = ei;
    const int* col = ei + E;

    void* p;
    float *dis, *enorm, *bufA, *bufB;
    int *cnt, *rowptr, *cursor, *csrcols, *part;
    cudaGetSymbolAddress(&p, g_dis);    dis = (float*)p;
    cudaGetSymbolAddress(&p, g_cnt);    cnt = (int*)p;
    cudaGetSymbolAddress(&p, g_rowptr); rowptr = (int*)p;
    cudaGetSymbolAddress(&p, g_cursor); cursor = (int*)p;
    cudaGetSymbolAddress(&p, g_part);   part = (int*)p;
    cudaGetSymbolAddress(&p, g_cols);   csrcols = (int*)p;
    cudaGetSymbolAddress(&p, g_enorm);  enorm = (float*)p;
    cudaGetSymbolAddress(&p, g_bufA);   bufA = (float*)p;
    cudaGetSymbolAddress(&p, g_bufB);   bufB = (float*)p;

    float* out = (float*)d_out;

    // ---- preprocessing (shared across layers) ----
    k_init<<<cdiv(N, 256), 256>>>(dis, cnt, N);
    k_edge_deg<<<cdiv(E, 256), 256>>>(row, ew, dis, cnt, E);
    k_dis<<<cdiv(N, 256), 256>>>(dis, N);
    int NB = cdiv(N, 256);
    k_reduce<<<NB, 256>>>(cnt, part, N);
    k_scanp<<<1, 256>>>(part, NB);
    k_apply<<<NB, 256>>>(cnt, part, rowptr, cursor, N, E);
    k_scatter<<<cdiv(E, 256), 256>>>(row, col, ew, dis, cursor, csrcols, enorm, E);

    int aggBlocks = cdiv(N * 32, 256);

    // ---- layer 0: 128 -> 100 ----
    k_gemm<<<dim3(cdiv(N, BM), cdiv(100, BN)), 256>>>(x, 128, W0, bufA, 100, N, 128, 100);
    k_agg<<<aggBlocks, 256>>>(bufA, 100, rowptr, csrcols, enorm, dis, b0, bufB, 100, N, 100, 1);

    // ---- layer 1: 100 -> 100 ----
    k_gemm<<<dim3(cdiv(N, BM), cdiv(100, BN)), 256>>>(bufB, 100, W1, bufA, 100, N, 100, 100);
    k_agg<<<aggBlocks, 256>>>(bufA, 100, rowptr, csrcols, enorm, dis, b1, bufB, 100, N, 100, 1);

    // ---- layer 2: 100 -> 50 (pad stride 52) ----
    k_gemm<<<dim3(cdiv(N, BM), cdiv(52, BN)), 256>>>(bufB, 100, W2, bufA, 52, N, 100, 50);
    k_agg<<<aggBlocks, 256>>>(bufA, 52, rowptr, csrcols, enorm, dis, b2, bufB, 52, N, 50, 1);

    // ---- layer 3: 50 -> 6 (pad stride 8), no relu, exact-width store to d_out ----
    k_gemm<<<dim3(cdiv(N, BM), 1), 256>>>(bufB, 52, W3, bufA, 8, N, 50, 6);
    k_agg<<<aggBlocks, 256>>>(bufA, 8, rowptr, csrcols, enorm, dis, b3, out, 6, N, 6, 0);
}

// round 14
// speedup vs baseline: 1.0073x; 1.0073x over previous
#include <cuda_runtime.h>
#include <cstdint>
#include <cstddef>

// ---------------- static scratch (no allocations allowed) ----------------
#define MAXN 50000
#define MAXE 800000

__device__ float g_dis[MAXN];          // degree, then D^-1/2 in place
__device__ int   g_cnt[MAXN];          // per-row edge counts
__device__ int   g_rowptr[MAXN + 1];
__device__ int   g_cursor[MAXN];
__device__ int   g_part[256];          // scan partials
__device__ int   g_cols[MAXE];         // CSR-sorted column ids
__device__ float g_enorm[MAXE];        // CSR-sorted per-edge norm
__device__ float g_bufA[MAXN * 100];   // 20 MB
__device__ float g_bufB[MAXN * 100];   // 20 MB

// ---------------- preprocessing kernels ----------------
__global__ void k_init(float* deg, int* cnt, int n) {
    int i = blockIdx.x * blockDim.x + threadIdx.x;
    if (i < n) { deg[i] = 1.0f; cnt[i] = 0; }   // self loop weight 1
}

__global__ void k_edge_deg(const int* __restrict__ row, const float* __restrict__ w,
                           float* deg, int* cnt, int e) {
    int i = blockIdx.x * blockDim.x + threadIdx.x;
    if (i < e) {
        int r = row[i];
        atomicAdd(&deg[r], w[i]);
        atomicAdd(&cnt[r], 1);
    }
}

__global__ void k_dis(float* deg, int n) {
    int i = blockIdx.x * blockDim.x + threadIdx.x;
    if (i < n) deg[i] = rsqrtf(deg[i]);   // deg >= 1 always
}

// ---- multi-block exclusive scan: reduce -> scan partials -> apply ----
__global__ void k_reduce(const int* __restrict__ cnt, int* __restrict__ part, int n) {
    __shared__ int ws[8];
    int i = blockIdx.x * 256 + threadIdx.x;
    int v = (i < n) ? cnt[i] : 0;
    #pragma unroll
    for (int off = 16; off > 0; off >>= 1) v += __shfl_down_sync(0xffffffffu, v, off);
    int lane = threadIdx.x & 31, w = threadIdx.x >> 5;
    if (lane == 0) ws[w] = v;
    __syncthreads();
    if (threadIdx.x == 0) {
        int s = 0;
        #pragma unroll
        for (int j = 0; j < 8; j++) s += ws[j];
        part[blockIdx.x] = s;
    }
}

// single block of 256 threads: exclusive scan of nb (<=256) partials, in place
__global__ void k_scanp(int* part, int nb) {
    __shared__ int ws[8];
    int tid = threadIdx.x;
    int lane = tid & 31, w = tid >> 5;
    int v = (tid < nb) ? part[tid] : 0;
    int x = v;
    #pragma unroll
    for (int off = 1; off < 32; off <<= 1) {
        int t = __shfl_up_sync(0xffffffffu, x, off);
        if (lane >= off) x += t;
    }
    if (lane == 31) ws[w] = x;
    __syncthreads();
    if (w == 0 && lane < 8) {
        int s = ws[lane];
        #pragma unroll
        for (int off = 1; off < 8; off <<= 1) {
            int t = __shfl_up_sync(0x000000ffu, s, off);
            if (lane >= off) s += t;
        }
        ws[lane] = s;
    }
    __syncthreads();
    int warp_excl = (w == 0) ? 0 : ws[w - 1];
    if (tid < nb) part[tid] = x + warp_excl - v;   // exclusive
}

__global__ void k_apply(const int* __restrict__ cnt, const int* __restrict__ part,
                        int* __restrict__ rowptr, int* __restrict__ cursor,
                        int n, int e) {
    __shared__ int ws[8];
    int tid = threadIdx.x;
    int lane = tid & 31, w = tid >> 5;
    int i = blockIdx.x * 256 + tid;
    int v = (i < n) ? cnt[i] : 0;
    int x = v;
    #pragma unroll
    for (int off = 1; off < 32; off <<= 1) {
        int t = __shfl_up_sync(0xffffffffu, x, off);
        if (lane >= off) x += t;
    }
    if (lane == 31) ws[w] = x;
    __syncthreads();
    if (w == 0 && lane < 8) {
        int s = ws[lane];
        #pragma unroll
        for (int off = 1; off < 8; off <<= 1) {
            int t = __shfl_up_sync(0x000000ffu, s, off);
            if (lane >= off) s += t;
        }
        ws[lane] = s;
    }
    __syncthreads();
    int warp_excl = (w == 0) ? 0 : ws[w - 1];
    int excl = x - v + warp_excl + part[blockIdx.x];
    if (i < n) { rowptr[i] = excl; cursor[i] = excl; }
    if (blockIdx.x == 0 && tid == 0) rowptr[n] = e;
}

__global__ void k_scatter(const int* __restrict__ row, const int* __restrict__ col,
                          const float* __restrict__ w, const float* __restrict__ dis,
                          int* cursor, int* __restrict__ ocol, float* __restrict__ onorm,
                          int e) {
    int i = blockIdx.x * blockDim.x + threadIdx.x;
    if (i < e) {
        int r = row[i];
        int c = col[i];
        int p = atomicAdd(&cursor[r], 1);
        ocol[p] = c;
        onorm[p] = dis[r] * w[i] * dis[c];
    }
}

// ---------------- GEMM: C[N x ldc] = A[N x K](lda) * B[K x F], pad cols zeroed ----------------
// 128x64 tile, BK=8, 256 threads, per-thread 8x4 register tile.
// Requires lda % 4 == 0 (holds: 128, 100, 100, 52).
#define BM 128
#define BN 64
#define BK 8

__global__ __launch_bounds__(256) void k_gemm(
    const float* __restrict__ A, int lda,
    const float* __restrict__ B,           // [K x F] row-major, stride F
    float* __restrict__ C, int ldc,
    int N, int K, int F) {
    __shared__ float As[BK][BM];
    __shared__ float Bs[BK][BN];

    int tid = threadIdx.x;
    int m0 = blockIdx.x * BM;
    int n0 = blockIdx.y * BN;
    int tx = tid & 15;   // 0..15 -> n
    int ty = tid >> 4;   // 0..15 -> m

    float acc[8][4];
    #pragma unroll
    for (int i = 0; i < 8; i++)
        #pragma unroll
        for (int j = 0; j < 4; j++) acc[i][j] = 0.f;

    for (int k0 = 0; k0 < K; k0 += BK) {
        // A tile: 128 rows x 8 k = 256 float4 loads, one per thread
        {
            int m  = tid >> 1;
            int kq = (tid & 1) * 4;
            int gm = m0 + m, gk = k0 + kq;
            float4 v = make_float4(0.f, 0.f, 0.f, 0.f);
            if (gm < N) {
                if (gk + 3 < K) {
                    v = *reinterpret_cast<const float4*>(A + (size_t)gm * lda + gk);
                } else {
                    const float* ar = A + (size_t)gm * lda;
                    if (gk + 0 < K) v.x = ar[gk + 0];
                    if (gk + 1 < K) v.y = ar[gk + 1];
                    if (gk + 2 < K) v.z = ar[gk + 2];
                    if (gk + 3 < K) v.w = ar[gk + 3];
                }
            }
            As[kq + 0][m] = v.x;
            As[kq + 1][m] = v.y;
            As[kq + 2][m] = v.z;
            As[kq + 3][m] = v.w;
        }
        // B tile: 8 x 64 = 512 elems, 2 per thread, coalesced
        #pragma unroll
        for (int i = 0; i < 2; i++) {
            int idx = tid + 256 * i;
            int k = idx >> 6;
            int nn = idx & 63;
            int gk = k0 + k, gn = n0 + nn;
            Bs[k][nn] = (gk < K && gn < F) ? B[(size_t)gk * F + gn] : 0.f;
        }
        __syncthreads();
        #pragma unroll
        for (int k = 0; k < BK; k++) {
            float4 a0 = *reinterpret_cast<const float4*>(&As[k][ty * 8]);
            float4 a1 = *reinterpret_cast<const float4*>(&As[k][ty * 8 + 4]);
            float4 b4 = *reinterpret_cast<const float4*>(&Bs[k][tx * 4]);
            float a[8] = {a0.x, a0.y, a0.z, a0.w, a1.x, a1.y, a1.z, a1.w};
            float b[4] = {b4.x, b4.y, b4.z, b4.w};
            #pragma unroll
            for (int i = 0; i < 8; i++)
                #pragma unroll
                for (int j = 0; j < 4; j++) acc[i][j] += a[i] * b[j];
        }
        __syncthreads();
    }

    #pragma unroll
    for (int i = 0; i < 8; i++) {
        int gm = m0 + ty * 8 + i;
        if (gm >= N) continue;
        #pragma unroll
        for (int j = 0; j < 4; j++) {
            int gn = n0 + tx * 4 + j;
            if (gn < F)        C[(size_t)gm * ldc + gn] = acc[i][j];
            else if (gn < ldc) C[(size_t)gm * ldc + gn] = 0.f;
        }
    }
}

// ---------------- aggregation: out[r] = bias + sum_e norm*h[col] + dis[r]^2*h[r] ----------------
// one warp per row; lane owns features [4*lane, 4*lane+4) of the padded stride SP
__global__ __launch_bounds__(256) void k_agg(
    const float* __restrict__ h, int SP,
    const int* __restrict__ rowptr,
    const int* __restrict__ cols,
    const float* __restrict__ enorm,
    const float* __restrict__ dis,
    const float* __restrict__ bias,
    float* __restrict__ out, int OS,
    int n, int F, int do_relu) {
    int wid = (blockIdx.x * blockDim.x + threadIdx.x) >> 5;
    int lane = threadIdx.x & 31;
    if (wid >= n) return;
    int row = wid;
    int f0 = lane * 4;
    bool active = f0 < SP;

    float4 acc0 = make_float4(0.f, 0.f, 0.f, 0.f);
    float4 acc1 = make_float4(0.f, 0.f, 0.f, 0.f);
    if (active) {
        float d = dis[row];
        float sn = d * d;
        float4 hv = *reinterpret_cast<const float4*>(h + (size_t)row * SP + f0);
        acc0.x = sn * hv.x + ((f0 + 0 < F) ? bias[f0 + 0] : 0.f);
        acc0.y = sn * hv.y + ((f0 + 1 < F) ? bias[f0 + 1] : 0.f);
        acc0.z = sn * hv.z + ((f0 + 2 < F) ? bias[f0 + 2] : 0.f);
        acc0.w = sn * hv.w + ((f0 + 3 < F) ? bias[f0 + 3] : 0.f);
    }

    int start = rowptr[row];
    int end = rowptr[row + 1];
    for (int eb = start; eb < end; eb += 32) {
        int idx = eb + lane;
        int c_l = 0;
        float v_l = 0.f;
        if (idx < end) { c_l = cols[idx]; v_l = enorm[idx]; }
        int cnt = min(32, end - eb);
        int i = 0;
        for (; i + 1 < cnt; i += 2) {
            int c0 = __shfl_sync(0xffffffffu, c_l, i);
            float v0 = __shfl_sync(0xffffffffu, v_l, i);
            int c1 = __shfl_sync(0xffffffffu, c_l, i + 1);
            float v1 = __shfl_sync(0xffffffffu, v_l, i + 1);
            if (active) {
                float4 h0 = *reinterpret_cast<const float4*>(h + (size_t)c0 * SP + f0);
                float4 h1 = *reinterpret_cast<const float4*>(h + (size_t)c1 * SP + f0);
                acc0.x += v0 * h0.x; acc0.y += v0 * h0.y;
                acc0.z += v0 * h0.z; acc0.w += v0 * h0.w;
                acc1.x += v1 * h1.x; acc1.y += v1 * h1.y;
                acc1.z += v1 * h1.z; acc1.w += v1 * h1.w;
            }
        }
        if (i < cnt) {
            int c0 = __shfl_sync(0xffffffffu, c_l, i);
            float v0 = __shfl_sync(0xffffffffu, v_l, i);
            if (active) {
                float4 h0 = *reinterpret_cast<const float4*>(h + (size_t)c0 * SP + f0);
                acc0.x += v0 * h0.x; acc0.y += v0 * h0.y;
                acc0.z += v0 * h0.z; acc0.w += v0 * h0.w;
            }
        }
    }
    if (!active) return;
    float4 acc = make_float4(acc0.x + acc1.x, acc0.y + acc1.y,
                             acc0.z + acc1.z, acc0.w + acc1.w);
    if (do_relu) {
        acc.x = fmaxf(acc.x, 0.f);
        acc.y = fmaxf(acc.y, 0.f);
        acc.z = fmaxf(acc.z, 0.f);
        acc.w = fmaxf(acc.w, 0.f);
    }
    if (OS == SP) {
        *reinterpret_cast<float4*>(out + (size_t)row * OS + f0) = acc;
    } else {
        float a[4] = {acc.x, acc.y, acc.z, acc.w};
        #pragma unroll
        for (int j = 0; j < 4; j++) {
            int f = f0 + j;
            if (f < OS) out[(size_t)row * OS + f] = a[j];
        }
    }
}

// ---------------- launch ----------------
static inline int cdiv(int a, int b) { return (a + b - 1) / b; }

extern "C" void kernel_launch(void* const* d_in, const int* in_sizes, int n_in,
                              void* d_out, int out_size) {
    const float* x  = (const float*)d_in[0];
    const int*   ei = (const int*)d_in[1];
    const float* ew = (const float*)d_in[2];
    const float* W0 = (const float*)d_in[3];
    const float* b0 = (const float*)d_in[4];
    const float* W1 = (const float*)d_in[5];
    const float* b1 = (const float*)d_in[6];
    const float* W2 = (const float*)d_in[7];
    const float* b2 = (const float*)d_in[8];
    const float* W3 = (const float*)d_in[9];
    const float* b3 = (const float*)d_in[10];

    int N = in_sizes[0] / 128;
    int E = in_sizes[1] / 2;
    const int* row = ei;
    const int* col = ei + E;

    void* p;
    float *dis, *enorm, *bufA, *bufB;
    int *cnt, *rowptr, *cursor, *csrcols, *part;
    cudaGetSymbolAddress(&p, g_dis);    dis = (float*)p;
    cudaGetSymbolAddress(&p, g_cnt);    cnt = (int*)p;
    cudaGetSymbolAddress(&p, g_rowptr); rowptr = (int*)p;
    cudaGetSymbolAddress(&p, g_cursor); cursor = (int*)p;
    cudaGetSymbolAddress(&p, g_part);   part = (int*)p;
    cudaGetSymbolAddress(&p, g_cols);   csrcols = (int*)p;
    cudaGetSymbolAddress(&p, g_enorm);  enorm = (float*)p;
    cudaGetSymbolAddress(&p, g_bufA);   bufA = (float*)p;
    cudaGetSymbolAddress(&p, g_bufB);   bufB = (float*)p;

    float* out = (float*)d_out;

    // ---- preprocessing (shared across layers) ----
    k_init<<<cdiv(N, 256), 256>>>(dis, cnt, N);
    k_edge_deg<<<cdiv(E, 256), 256>>>(row, ew, dis, cnt, E);
    k_dis<<<cdiv(N, 256), 256>>>(dis, N);
    int NB = cdiv(N, 256);
    k_reduce<<<NB, 256>>>(cnt, part, N);
    k_scanp<<<1, 256>>>(part, NB);
    k_apply<<<NB, 256>>>(cnt, part, rowptr, cursor, N, E);
    k_scatter<<<cdiv(E, 256), 256>>>(row, col, ew, dis, cursor, csrcols, enorm, E);

    int aggBlocks = cdiv(N * 32, 256);

    // ---- layer 0: 128 -> 100 ----
    k_gemm<<<dim3(cdiv(N, BM), cdiv(100, BN)), 256>>>(x, 128, W0, bufA, 100, N, 128, 100);
    k_agg<<<aggBlocks, 256>>>(bufA, 100, rowptr, csrcols, enorm, dis, b0, bufB, 100, N, 100, 1);

    // ---- layer 1: 100 -> 100 ----
    k_gemm<<<dim3(cdiv(N, BM), cdiv(100, BN)), 256>>>(bufB, 100, W1, bufA, 100, N, 100, 100);
    k_agg<<<aggBlocks, 256>>>(bufA, 100, rowptr, csrcols, enorm, dis, b1, bufB, 100, N, 100, 1);

    // ---- layer 2: 100 -> 50 (pad stride 52) ----
    k_gemm<<<dim3(cdiv(N, BM), cdiv(52, BN)), 256>>>(bufB, 100, W2, bufA, 52, N, 100, 50);
    k_agg<<<aggBlocks, 256>>>(bufA, 52, rowptr, csrcols, enorm, dis, b2, bufB, 52, N, 50, 1);

    // ---- layer 3: 50 -> 6 (pad stride 8), no relu, exact-width store to d_out ----
    k_gemm<<<dim3(cdiv(N, BM), 1), 256>>>(bufB, 52, W3, bufA, 8, N, 50, 6);
    k_agg<<<aggBlocks, 256>>>(bufA, 8, rowptr, csrcols, enorm, dis, b3, out, 6, N, 6, 0);
}

// round 15
// speedup vs baseline: 1.0127x; 1.0053x over previous
#include <cuda_runtime.h>
#include <cstdint>
#include <cstddef>

// ---------------- static scratch (no allocations allowed) ----------------
#define MAXN 50000
#define MAXE 800000

__device__ float g_dis[MAXN];          // degree, then D^-1/2 in place
__device__ int   g_cnt[MAXN];          // per-row edge counts
__device__ int   g_rowptr[MAXN + 1];
__device__ int   g_cursor[MAXN];
__device__ int   g_part[256];          // scan partials
__device__ int   g_cols[MAXE];         // CSR-sorted column ids
__device__ float g_enorm[MAXE];        // CSR-sorted per-edge norm
__device__ float g_bufA[MAXN * 100];   // 20 MB
__device__ float g_bufB[MAXN * 100];   // 20 MB

// ---------------- preprocessing kernels ----------------
__global__ void k_init(float* deg, int* cnt, int n) {
    int i = blockIdx.x * blockDim.x + threadIdx.x;
    if (i < n) { deg[i] = 1.0f; cnt[i] = 0; }   // self loop weight 1
}

__global__ void k_edge_deg(const int* __restrict__ row, const float* __restrict__ w,
                           float* deg, int* cnt, int e) {
    int i = blockIdx.x * blockDim.x + threadIdx.x;
    if (i < e) {
        int r = row[i];
        atomicAdd(&deg[r], w[i]);
        atomicAdd(&cnt[r], 1);
    }
}

__global__ void k_dis(float* deg, int n) {
    int i = blockIdx.x * blockDim.x + threadIdx.x;
    if (i < n) deg[i] = rsqrtf(deg[i]);   // deg >= 1 always
}

// ---- multi-block exclusive scan: reduce -> scan partials -> apply ----
__global__ void k_reduce(const int* __restrict__ cnt, int* __restrict__ part, int n) {
    __shared__ int ws[8];
    int i = blockIdx.x * 256 + threadIdx.x;
    int v = (i < n) ? cnt[i] : 0;
    #pragma unroll
    for (int off = 16; off > 0; off >>= 1) v += __shfl_down_sync(0xffffffffu, v, off);
    int lane = threadIdx.x & 31, w = threadIdx.x >> 5;
    if (lane == 0) ws[w] = v;
    __syncthreads();
    if (threadIdx.x == 0) {
        int s = 0;
        #pragma unroll
        for (int j = 0; j < 8; j++) s += ws[j];
        part[blockIdx.x] = s;
    }
}

// single block of 256 threads: exclusive scan of nb (<=256) partials, in place
__global__ void k_scanp(int* part, int nb) {
    __shared__ int ws[8];
    int tid = threadIdx.x;
    int lane = tid & 31, w = tid >> 5;
    int v = (tid < nb) ? part[tid] : 0;
    int x = v;
    #pragma unroll
    for (int off = 1; off < 32; off <<= 1) {
        int t = __shfl_up_sync(0xffffffffu, x, off);
        if (lane >= off) x += t;
    }
    if (lane == 31) ws[w] = x;
    __syncthreads();
    if (w == 0 && lane < 8) {
        int s = ws[lane];
        #pragma unroll
        for (int off = 1; off < 8; off <<= 1) {
            int t = __shfl_up_sync(0x000000ffu, s, off);
            if (lane >= off) s += t;
        }
        ws[lane] = s;
    }
    __syncthreads();
    int warp_excl = (w == 0) ? 0 : ws[w - 1];
    if (tid < nb) part[tid] = x + warp_excl - v;   // exclusive
}

__global__ void k_apply(const int* __restrict__ cnt, const int* __restrict__ part,
                        int* __restrict__ rowptr, int* __restrict__ cursor,
                        int n, int e) {
    __shared__ int ws[8];
    int tid = threadIdx.x;
    int lane = tid & 31, w = tid >> 5;
    int i = blockIdx.x * 256 + tid;
    int v = (i < n) ? cnt[i] : 0;
    int x = v;
    #pragma unroll
    for (int off = 1; off < 32; off <<= 1) {
        int t = __shfl_up_sync(0xffffffffu, x, off);
        if (lane >= off) x += t;
    }
    if (lane == 31) ws[w] = x;
    __syncthreads();
    if (w == 0 && lane < 8) {
        int s = ws[lane];
        #pragma unroll
        for (int off = 1; off < 8; off <<= 1) {
            int t = __shfl_up_sync(0x000000ffu, s, off);
            if (lane >= off) s += t;
        }
        ws[lane] = s;
    }
    __syncthreads();
    int warp_excl = (w == 0) ? 0 : ws[w - 1];
    int excl = x - v + warp_excl + part[blockIdx.x];
    if (i < n) { rowptr[i] = excl; cursor[i] = excl; }
    if (blockIdx.x == 0 && tid == 0) rowptr[n] = e;
}

__global__ void k_scatter(const int* __restrict__ row, const int* __restrict__ col,
                          const float* __restrict__ w, const float* __restrict__ dis,
                          int* cursor, int* __restrict__ ocol, float* __restrict__ onorm,
                          int e) {
    int i = blockIdx.x * blockDim.x + threadIdx.x;
    if (i < e) {
        int r = row[i];
        int c = col[i];
        int p = atomicAdd(&cursor[r], 1);
        ocol[p] = c;
        onorm[p] = dis[r] * w[i] * dis[c];
    }
}

// ---------------- GEMM: C[N x ldc] = A[N x K](lda) * B[K x F], pad cols zeroed ----------------
// 128x64 tile, BK=8, 256 threads, per-thread 8x4 register tile.
// Requires lda % 4 == 0 (holds: 128, 100, 100, 52).
#define BM 128
#define BN 64
#define BK 8

__global__ __launch_bounds__(256) void k_gemm(
    const float* __restrict__ A, int lda,
    const float* __restrict__ B,           // [K x F] row-major, stride F
    float* __restrict__ C, int ldc,
    int N, int K, int F) {
    __shared__ float As[BK][BM];
    __shared__ float Bs[BK][BN];

    int tid = threadIdx.x;
    int m0 = blockIdx.x * BM;
    int n0 = blockIdx.y * BN;
    int tx = tid & 15;   // 0..15 -> n
    int ty = tid >> 4;   // 0..15 -> m

    float acc[8][4];
    #pragma unroll
    for (int i = 0; i < 8; i++)
        #pragma unroll
        for (int j = 0; j < 4; j++) acc[i][j] = 0.f;

    for (int k0 = 0; k0 < K; k0 += BK) {
        // A tile: 128 rows x 8 k = 256 float4 loads, one per thread
        {
            int m  = tid >> 1;
            int kq = (tid & 1) * 4;
            int gm = m0 + m, gk = k0 + kq;
            float4 v = make_float4(0.f, 0.f, 0.f, 0.f);
            if (gm < N) {
                if (gk + 3 < K) {
                    v = *reinterpret_cast<const float4*>(A + (size_t)gm * lda + gk);
                } else {
                    const float* ar = A + (size_t)gm * lda;
                    if (gk + 0 < K) v.x = ar[gk + 0];
                    if (gk + 1 < K) v.y = ar[gk + 1];
                    if (gk + 2 < K) v.z = ar[gk + 2];
                    if (gk + 3 < K) v.w = ar[gk + 3];
                }
            }
            As[kq + 0][m] = v.x;
            As[kq + 1][m] = v.y;
            As[kq + 2][m] = v.z;
            As[kq + 3][m] = v.w;
        }
        // B tile: 8 x 64 = 512 elems, 2 per thread, coalesced
        #pragma unroll
        for (int i = 0; i < 2; i++) {
            int idx = tid + 256 * i;
            int k = idx >> 6;
            int nn = idx & 63;
            int gk = k0 + k, gn = n0 + nn;
            Bs[k][nn] = (gk < K && gn < F) ? B[(size_t)gk * F + gn] : 0.f;
        }
        __syncthreads();
        #pragma unroll
        for (int k = 0; k < BK; k++) {
            float4 a0 = *reinterpret_cast<const float4*>(&As[k][ty * 8]);
            float4 a1 = *reinterpret_cast<const float4*>(&As[k][ty * 8 + 4]);
            float4 b4 = *reinterpret_cast<const float4*>(&Bs[k][tx * 4]);
            float a[8] = {a0.x, a0.y, a0.z, a0.w, a1.x, a1.y, a1.z, a1.w};
            float b[4] = {b4.x, b4.y, b4.z, b4.w};
            #pragma unroll
            for (int i = 0; i < 8; i++)
                #pragma unroll
                for (int j = 0; j < 4; j++) acc[i][j] += a[i] * b[j];
        }
        __syncthreads();
    }

    #pragma unroll
    for (int i = 0; i < 8; i++) {
        int gm = m0 + ty * 8 + i;
        if (gm >= N) continue;
        #pragma unroll
        for (int j = 0; j < 4; j++) {
            int gn = n0 + tx * 4 + j;
            if (gn < F)        C[(size_t)gm * ldc + gn] = acc[i][j];
            else if (gn < ldc) C[(size_t)gm * ldc + gn] = 0.f;
        }
    }
}

// ---------------- aggregation: out[r] = bias + sum_e norm*h[col] + dis[r]^2*h[r] ----------------
// one warp per row; lane owns features [4*lane, 4*lane+4) of the padded stride SP
__global__ __launch_bounds__(256) void k_agg(
    const float* __restrict__ h, int SP,
    const int* __restrict__ rowptr,
    const int* __restrict__ cols,
    const float* __restrict__ enorm,
    const float* __restrict__ dis,
    const float* __restrict__ bias,
    float* __restrict__ out, int OS,
    int n, int F, int do_relu) {
    int wid = (blockIdx.x * blockDim.x + threadIdx.x) >> 5;
    int lane = threadIdx.x & 31;
    if (wid >= n) return;
    int row = wid;
    int f0 = lane * 4;
    bool active = f0 < SP;

    float4 acc0 = make_float4(0.f, 0.f, 0.f, 0.f);
    float4 acc1 = make_float4(0.f, 0.f, 0.f, 0.f);
    if (active) {
        float d = dis[row];
        float sn = d * d;
        float4 hv = *reinterpret_cast<const float4*>(h + (size_t)row * SP + f0);
        acc0.x = sn * hv.x + ((f0 + 0 < F) ? bias[f0 + 0] : 0.f);
        acc0.y = sn * hv.y + ((f0 + 1 < F) ? bias[f0 + 1] : 0.f);
        acc0.z = sn * hv.z + ((f0 + 2 < F) ? bias[f0 + 2] : 0.f);
        acc0.w = sn * hv.w + ((f0 + 3 < F) ? bias[f0 + 3] : 0.f);
    }

    int start = rowptr[row];
    int end = rowptr[row + 1];
    for (int eb = start; eb < end; eb += 32) {
        int idx = eb + lane;
        int c_l = 0;
        float v_l = 0.f;
        if (idx < end) { c_l = cols[idx]; v_l = enorm[idx]; }
        int cnt = min(32, end - eb);
        int i = 0;
        for (; i + 1 < cnt; i += 2) {
            int c0 = __shfl_sync(0xffffffffu, c_l, i);
            float v0 = __shfl_sync(0xffffffffu, v_l, i);
            int c1 = __shfl_sync(0xffffffffu, c_l, i + 1);
            float v1 = __shfl_sync(0xffffffffu, v_l, i + 1);
            if (active) {
                float4 h0 = *reinterpret_cast<const float4*>(h + (size_t)c0 * SP + f0);
                float4 h1 = *reinterpret_cast<const float4*>(h + (size_t)c1 * SP + f0);
                acc0.x += v0 * h0.x; acc0.y += v0 * h0.y;
                acc0.z += v0 * h0.z; acc0.w += v0 * h0.w;
                acc1.x += v1 * h1.x; acc1.y += v1 * h1.y;
                acc1.z += v1 * h1.z; acc1.w += v1 * h1.w;
            }
        }
        if (i < cnt) {
            int c0 = __shfl_sync(0xffffffffu, c_l, i);
            float v0 = __shfl_sync(0xffffffffu, v_l, i);
            if (active) {
                float4 h0 = *reinterpret_cast<const float4*>(h + (size_t)c0 * SP + f0);
                acc0.x += v0 * h0.x; acc0.y += v0 * h0.y;
                acc0.z += v0 * h0.z; acc0.w += v0 * h0.w;
            }
        }
    }
    if (!active) return;
    float4 acc = make_float4(acc0.x + acc1.x, acc0.y + acc1.y,
                             acc0.z + acc1.z, acc0.w + acc1.w);
    if (do_relu) {
        acc.x = fmaxf(acc.x, 0.f);
        acc.y = fmaxf(acc.y, 0.f);
        acc.z = fmaxf(acc.z, 0.f);
        acc.w = fmaxf(acc.w, 0.f);
    }
    if (OS == SP) {
        *reinterpret_cast<float4*>(out + (size_t)row * OS + f0) = acc;
    } else {
        float a[4] = {acc.x, acc.y, acc.z, acc.w};
        #pragma unroll
        for (int j = 0; j < 4; j++) {
            int f = f0 + j;
            if (f < OS) out[(size_t)row * OS + f] = a[j];
        }
    }
}

// ---------------- launch ----------------
static inline int cdiv(int a, int b) { return (a + b - 1) / b; }

extern "C" void kernel_launch(void* const* d_in, const int* in_sizes, int n_in,
                              void* d_out, int out_size) {
    const float* x  = (const float*)d_in[0];
    const int*   ei = (const int*)d_in[1];
    const float* ew = (const float*)d_in[2];
    const float* W0 = (const float*)d_in[3];
    const float* b0 = (const float*)d_in[4];
    const float* W1 = (const float*)d_in[5];
    const float* b1 = (const float*)d_in[6];
    const float* W2 = (const float*)d_in[7];
    const float* b2 = (const float*)d_in[8];
    const float* W3 = (const float*)d_in[9];
    const float* b3 = (const float*)d_in[10];

    int N = in_sizes[0] / 128;
    int E = in_sizes[1] / 2;
    const int* row = ei;
    const int* col = ei + E;

    void* p;
    float *dis, *enorm, *bufA, *bufB;
    int *cnt, *rowptr, *cursor, *csrcols, *part;
    cudaGetSymbolAddress(&p, g_dis);    dis = (float*)p;
    cudaGetSymbolAddress(&p, g_cnt);    cnt = (int*)p;
    cudaGetSymbolAddress(&p, g_rowptr); rowptr = (int*)p;
    cudaGetSymbolAddress(&p, g_cursor); cursor = (int*)p;
    cudaGetSymbolAddress(&p, g_part);   part = (int*)p;
    cudaGetSymbolAddress(&p, g_cols);   csrcols = (int*)p;
    cudaGetSymbolAddress(&p, g_enorm);  enorm = (float*)p;
    cudaGetSymbolAddress(&p, g_bufA);   bufA = (float*)p;
    cudaGetSymbolAddress(&p, g_bufB);   bufB = (float*)p;

    float* out = (float*)d_out;

    // ---- preprocessing (shared across layers) ----
    k_init<<<cdiv(N, 256), 256>>>(dis, cnt, N);
    k_edge_deg<<<cdiv(E, 256), 256>>>(row, ew, dis, cnt, E);
    k_dis<<<cdiv(N, 256), 256>>>(dis, N);
    int NB = cdiv(N, 256);
    k_reduce<<<NB, 256>>>(cnt, part, N);
    k_scanp<<<1, 256>>>(part, NB);
    k_apply<<<NB, 256>>>(cnt, part, rowptr, cursor, N, E);
    k_scatter<<<cdiv(E, 256), 256>>>(row, col, ew, dis, cursor, csrcols, enorm, E);

    int aggBlocks = cdiv(N * 32, 256);

    // ---- layer 0: 128 -> 100 ----
    k_gemm<<<dim3(cdiv(N, BM), cdiv(100, BN)), 256>>>(x, 128, W0, bufA, 100, N, 128, 100);
    k_agg<<<aggBlocks, 256>>>(bufA, 100, rowptr, csrcols, enorm, dis, b0, bufB, 100, N, 100, 1);

    // ---- layer 1: 100 -> 100 ----
    k_gemm<<<dim3(cdiv(N, BM), cdiv(100, BN)), 256>>>(bufB, 100, W1, bufA, 100, N, 100, 100);
    k_agg<<<aggBlocks, 256>>>(bufA, 100, rowptr, csrcols, enorm, dis, b1, bufB, 100, N, 100, 1);

    // ---- layer 2: 100 -> 50 (pad stride 52) ----
    k_gemm<<<dim3(cdiv(N, BM), cdiv(52, BN)), 256>>>(bufB, 100, W2, bufA, 52, N, 100, 50);
    k_agg<<<aggBlocks, 256>>>(bufA, 52, rowptr, csrcols, enorm, dis, b2, bufB, 52, N, 50, 1);

    // ---- layer 3: 50 -> 6 (pad stride 8), no relu, exact-width store to d_out ----
    k_gemm<<<dim3(cdiv(N, BM), 1), 256>>>(bufB, 52, W3, bufA, 8, N, 50, 6);
    k_agg<<<aggBlocks, 256>>>(bufA, 8, rowptr, csrcols, enorm, dis, b3, out, 6, N, 6, 0);
}